// round 7
// baseline (speedup 1.0000x reference)
#include <cuda_runtime.h>
#include <math.h>

// Problem dims (fixed by setup_inputs)
#define MAXN 100000
#define MAXB 256
#define D2 50
#define D3 15
#define D2P 52
#define D5 10
#define NC 6

// ---------------- device scratch ----------------
// per-node record: 15 accum floats + count in slot 15 (16 floats = 64B)
__device__ __align__(16) float g_x2sum[MAXN * 16];

// ---------------- packed f32x2 helpers ----------------
__device__ __forceinline__ unsigned long long pack2(float a, float b) {
    unsigned long long r;
    asm("mov.b64 %0, {%1, %2};" : "=l"(r) : "f"(a), "f"(b));
    return r;
}
__device__ __forceinline__ void unpack2(unsigned long long v, float& a, float& b) {
    asm("mov.b64 {%0, %1}, %2;" : "=f"(a), "=f"(b) : "l"(v));
}
__device__ __forceinline__ void ffma2(unsigned long long& acc,
                                      unsigned long long a, unsigned long long b) {
    asm("fma.rn.f32x2 %0, %1, %2, %0;" : "+l"(acc) : "l"(a), "l"(b));
}
__device__ __forceinline__ void red4(float* p, float a, float b, float c, float d) {
    asm volatile("red.global.add.v4.f32 [%0], {%1, %2, %3, %4};"
                 :: "l"(p), "f"(a), "f"(b), "f"(c), "f"(d) : "memory");
}

// ---------------- zero accumulators ----------------
__global__ void zero_kernel(int N) {
    int tid = blockIdx.x * blockDim.x + threadIdx.x;
    int stride = gridDim.x * blockDim.x;
    int total = N * 4;  // float4 units
    float4 z = make_float4(0.f, 0.f, 0.f, 0.f);
    float4* p = reinterpret_cast<float4*>(g_x2sum);
    for (int t = tid; t < total; t += stride) p[t] = z;
}

// ---------------- SMEM weight layout (floats, 16B-aligned offsets) --------
// layer-1 weights: [in][52] padded rows (broadcast multiplicand scheme)
// layer-2 weights: j-pair transposed: [outs][52], float (k*52+j) = w2[j][k]
#define OFF_EW1  0                        // [9][52]
#define OFF_EB1  468                      // [52]
#define OFF_EW2P 520                      // [16][52]
#define OFF_EB2  1352                     // [16]
#define OFF_NW1  1368                     // [18][52]
#define OFF_NB1  2304                     // [52]
#define OFF_NW2P 2356                     // [16][52]
#define OFF_NB2  3188                     // [16]
#define SW_TOTAL 3204

// ---------------- edge kernel: 2 edges/thread, e2 spilled to shared -------
__global__ void __launch_bounds__(128, 4)
edge_kernel(
    const float* __restrict__ x,
    const int* __restrict__ row,
    const int* __restrict__ col,
    const float* __restrict__ ea,
    const float* __restrict__ ew1, const float* __restrict__ eb1,
    const float* __restrict__ ew2, const float* __restrict__ eb2,
    const float* __restrict__ nw1, const float* __restrict__ nb1,
    const float* __restrict__ nw2, const float* __restrict__ nb2,
    int P, int E)
{
    __shared__ __align__(16) float sw[SW_TOTAL];
    __shared__ float se2[30 * 128];   // e2 scratch: slot-major, lane-indexed

    for (int t = threadIdx.x; t < SW_TOTAL; t += blockDim.x) sw[t] = 0.0f;
    __syncthreads();
    for (int t = threadIdx.x; t < 9 * D2; t += blockDim.x) {
        int i = t / D2, j = t % D2;
        sw[OFF_EW1 + i * D2P + j] = ew1[t];
    }
    for (int t = threadIdx.x; t < D2; t += blockDim.x) sw[OFF_EB1 + t] = eb1[t];
    for (int t = threadIdx.x; t < D2 * D3; t += blockDim.x) {
        int j = t / D3, k = t % D3;
        sw[OFF_EW2P + k * D2P + j] = ew2[t];
    }
    for (int t = threadIdx.x; t < D3; t += blockDim.x) sw[OFF_EB2 + t] = eb2[t];
    for (int t = threadIdx.x; t < 18 * D2; t += blockDim.x) {
        int i = t / D2, j = t % D2;
        sw[OFF_NW1 + i * D2P + j] = nw1[t];
    }
    for (int t = threadIdx.x; t < D2; t += blockDim.x) sw[OFF_NB1 + t] = nb1[t];
    for (int t = threadIdx.x; t < D2 * D3; t += blockDim.x) {
        int j = t / D3, k = t % D3;
        sw[OFF_NW2P + k * D2P + j] = nw2[t];
    }
    for (int t = threadIdx.x; t < D3; t += blockDim.x) sw[OFF_NB2 + t] = nb2[t];
    __syncthreads();

    int tid = threadIdx.x;
    int p = blockIdx.x * blockDim.x + tid;
    if (p >= P) return;

    int e0 = 2 * p;
    int e1 = 2 * p + 1;
    bool validB = (e1 < E);

    // vectorized index loads: edges 2p,2p+1 are adjacent
    int rA, rB, cA, cB;
    if (validB) {
        int2 rr = reinterpret_cast<const int2*>(row)[p];
        int2 cc = reinterpret_cast<const int2*>(col)[p];
        rA = rr.x; rB = rr.y; cA = cc.x; cB = cc.y;
    } else {
        rA = row[e0]; cA = col[e0];
        rB = rA; cB = cA;
    }

    float inA[9], inB[9];
    inA[0] = x[3 * rA + 0]; inA[1] = x[3 * rA + 1]; inA[2] = x[3 * rA + 2];
    inA[3] = x[3 * cA + 0]; inA[4] = x[3 * cA + 1]; inA[5] = x[3 * cA + 2];
    inB[0] = x[3 * rB + 0]; inB[1] = x[3 * rB + 1]; inB[2] = x[3 * rB + 2];
    inB[3] = x[3 * cB + 0]; inB[4] = x[3 * cB + 1]; inB[5] = x[3 * cB + 2];
    if (validB) {
        const float2* ea2 = reinterpret_cast<const float2*>(ea);
        float2 a0 = ea2[3 * p + 0], a1 = ea2[3 * p + 1], a2 = ea2[3 * p + 2];
        inA[6] = a0.x; inA[7] = a0.y; inA[8] = a1.x;
        inB[6] = a1.y; inB[7] = a2.x; inB[8] = a2.y;
    } else {
        inA[6] = ea[3 * e0 + 0]; inA[7] = ea[3 * e0 + 1]; inA[8] = ea[3 * e0 + 2];
        inB[6] = inA[6]; inB[7] = inA[7]; inB[8] = inA[8];
    }
    float xcA0 = inA[3], xcA1 = inA[4], xcA2 = inA[5];
    float xcB0 = inB[3], xcB1 = inB[4], xcB2 = inB[5];

    // ==== edge MLP layer 1: h = relu(eb1 + in9 @ ew1)
    unsigned long long hA[26], hB[26];
    {
        const ulonglong2* bv = reinterpret_cast<const ulonglong2*>(&sw[OFF_EB1]);
        #pragma unroll
        for (int q2 = 0; q2 < 13; ++q2) {
            ulonglong2 b = bv[q2];
            hA[2 * q2] = b.x; hA[2 * q2 + 1] = b.y;
            hB[2 * q2] = b.x; hB[2 * q2 + 1] = b.y;
        }
    }
    #pragma unroll
    for (int i = 0; i < 9; ++i) {
        unsigned long long pa = pack2(inA[i], inA[i]);
        unsigned long long pb = pack2(inB[i], inB[i]);
        const ulonglong2* wv = reinterpret_cast<const ulonglong2*>(&sw[OFF_EW1 + i * D2P]);
        #pragma unroll
        for (int q2 = 0; q2 < 13; ++q2) {
            ulonglong2 w = wv[q2];
            ffma2(hA[2 * q2],     pa, w.x);
            ffma2(hA[2 * q2 + 1], pa, w.y);
            ffma2(hB[2 * q2],     pb, w.x);
            ffma2(hB[2 * q2 + 1], pb, w.y);
        }
    }
    #pragma unroll
    for (int q = 0; q < 26; ++q) {
        float a, b;
        unpack2(hA[q], a, b); hA[q] = pack2(fmaxf(a, 0.f), fmaxf(b, 0.f));
        unpack2(hB[q], a, b); hB[q] = pack2(fmaxf(a, 0.f), fmaxf(b, 0.f));
    }

    // ==== edge MLP layer 2 -> shared scratch (frees registers)
    #pragma unroll
    for (int k = 0; k < 15; ++k) {
        unsigned long long aA = 0ULL, aB = 0ULL;
        const ulonglong2* wp = reinterpret_cast<const ulonglong2*>(&sw[OFF_EW2P + k * D2P]);
        #pragma unroll
        for (int q2 = 0; q2 < 13; ++q2) {
            ulonglong2 w = wp[q2];
            ffma2(aA, hA[2 * q2],     w.x);
            ffma2(aA, hA[2 * q2 + 1], w.y);
            ffma2(aB, hB[2 * q2],     w.x);
            ffma2(aB, hB[2 * q2 + 1], w.y);
        }
        float lo, hi;
        float bk = sw[OFF_EB2 + k];
        unpack2(aA, lo, hi); se2[(2 * k + 0) * 128 + tid] = lo + hi + bk;
        unpack2(aB, lo, hi); se2[(2 * k + 1) * 128 + tid] = lo + hi + bk;
    }

    // ==== node MLP layer 1: h2 = relu(nb1 + [x[col], e2] @ nw1)
    unsigned long long h2A[26], h2B[26];
    {
        const ulonglong2* bv = reinterpret_cast<const ulonglong2*>(&sw[OFF_NB1]);
        #pragma unroll
        for (int q2 = 0; q2 < 13; ++q2) {
            ulonglong2 b = bv[q2];
            h2A[2 * q2] = b.x; h2A[2 * q2 + 1] = b.y;
            h2B[2 * q2] = b.x; h2B[2 * q2 + 1] = b.y;
        }
    }
    #pragma unroll
    for (int i = 0; i < 18; ++i) {
        float xa, xb;
        if (i == 0)      { xa = xcA0; xb = xcB0; }
        else if (i == 1) { xa = xcA1; xb = xcB1; }
        else if (i == 2) { xa = xcA2; xb = xcB2; }
        else {
            xa = se2[(2 * (i - 3) + 0) * 128 + tid];
            xb = se2[(2 * (i - 3) + 1) * 128 + tid];
        }
        unsigned long long pa = pack2(xa, xa);
        unsigned long long pb = pack2(xb, xb);
        const ulonglong2* wv = reinterpret_cast<const ulonglong2*>(&sw[OFF_NW1 + i * D2P]);
        #pragma unroll
        for (int q2 = 0; q2 < 13; ++q2) {
            ulonglong2 w = wv[q2];
            ffma2(h2A[2 * q2],     pa, w.x);
            ffma2(h2A[2 * q2 + 1], pa, w.y);
            ffma2(h2B[2 * q2],     pb, w.x);
            ffma2(h2B[2 * q2 + 1], pb, w.y);
        }
    }
    #pragma unroll
    for (int q = 0; q < 26; ++q) {
        float a, b;
        unpack2(h2A[q], a, b); h2A[q] = pack2(fmaxf(a, 0.f), fmaxf(b, 0.f));
        unpack2(h2B[q], a, b); h2B[q] = pack2(fmaxf(a, 0.f), fmaxf(b, 0.f));
    }

    // ==== node MLP layer 2: emit in 4-wide chunks straight to red4
    float* dstA = &g_x2sum[(size_t)rA * 16];
    float* dstB = &g_x2sum[(size_t)rB * 16];
    #pragma unroll
    for (int kc = 0; kc < 4; ++kc) {
        float vA[4], vB[4];
        #pragma unroll
        for (int t = 0; t < 4; ++t) {
            int k = 4 * kc + t;
            if (k < 15) {
                unsigned long long aA = 0ULL, aB = 0ULL;
                const ulonglong2* wp = reinterpret_cast<const ulonglong2*>(&sw[OFF_NW2P + k * D2P]);
                #pragma unroll
                for (int q2 = 0; q2 < 13; ++q2) {
                    ulonglong2 w = wp[q2];
                    ffma2(aA, h2A[2 * q2],     w.x);
                    ffma2(aA, h2A[2 * q2 + 1], w.y);
                    ffma2(aB, h2B[2 * q2],     w.x);
                    ffma2(aB, h2B[2 * q2 + 1], w.y);
                }
                float lo, hi;
                float bk = sw[OFF_NB2 + k];
                unpack2(aA, lo, hi); vA[t] = lo + hi + bk;
                unpack2(aB, lo, hi); vB[t] = lo + hi + bk;
            } else {
                vA[t] = 1.0f;  // count slot
                vB[t] = 1.0f;
            }
        }
        red4(dstA + 4 * kc, vA[0], vA[1], vA[2], vA[3]);
        if (validB) red4(dstB + 4 * kc, vB[0], vB[1], vB[2], vB[3]);
    }
}

// ---------------- graph kernel: per-graph reduce + global MLP + head -------
#define SG_GW1 0
#define SG_GB1 (SG_GW1 + 16 * D2)
#define SG_GW2 (SG_GB1 + D2)
#define SG_GB2 (SG_GW2 + D2 * D3)
#define SG_F1W (SG_GB2 + D3)
#define SG_F1B (SG_F1W + D3 * D5)
#define SG_BNG (SG_F1B + D5)
#define SG_BNB (SG_BNG + D5)
#define SG_F2W (SG_BNB + D5)
#define SG_F2B (SG_F2W + D5 * NC)
#define SG_TOTAL (SG_F2B + NC)

__device__ __forceinline__ int lbound(const int* a, int n, int key) {
    int lo = 0, hi = n;
    while (lo < hi) { int m = (lo + hi) >> 1; if (a[m] < key) lo = m + 1; else hi = m; }
    return lo;
}

__global__ void __launch_bounds__(256)
graph_kernel(
    const int* __restrict__ batch,
    const float* __restrict__ u,
    const float* __restrict__ gw1, const float* __restrict__ gb1,
    const float* __restrict__ gw2, const float* __restrict__ gb2,
    const float* __restrict__ fc1w, const float* __restrict__ fc1b,
    const float* __restrict__ bng, const float* __restrict__ bnb,
    const float* __restrict__ fc2w, const float* __restrict__ fc2b,
    float* __restrict__ out, int N)
{
    __shared__ float swt[SG_TOTAL];
    __shared__ float sred[8][30];
    __shared__ int sse[2];

    int tid = threadIdx.x;
    for (int t = tid; t < 16 * D2; t += blockDim.x) swt[SG_GW1 + t] = gw1[t];
    for (int t = tid; t < D2; t += blockDim.x) swt[SG_GB1 + t] = gb1[t];
    for (int t = tid; t < D2 * D3; t += blockDim.x) swt[SG_GW2 + t] = gw2[t];
    for (int t = tid; t < D3; t += blockDim.x) swt[SG_GB2 + t] = gb2[t];
    for (int t = tid; t < D3 * D5; t += blockDim.x) swt[SG_F1W + t] = fc1w[t];
    for (int t = tid; t < D5; t += blockDim.x) {
        swt[SG_F1B + t] = fc1b[t];
        swt[SG_BNG + t] = bng[t];
        swt[SG_BNB + t] = bnb[t];
    }
    for (int t = tid; t < D5 * NC; t += blockDim.x) swt[SG_F2W + t] = fc2w[t];
    for (int t = tid; t < NC; t += blockDim.x) swt[SG_F2B + t] = fc2b[t];

    int b = blockIdx.x;
    if (tid == 0) {
        sse[0] = lbound(batch, N, b);
        sse[1] = lbound(batch, N, b + 1);
    }
    __syncthreads();
    int s = sse[0], epos = sse[1];
    int nnodes = epos - s;

    float acc[30];
    #pragma unroll
    for (int k = 0; k < 30; ++k) acc[k] = 0.0f;

    for (int n = s + tid; n < epos; n += blockDim.x) {
        const float4* p = reinterpret_cast<const float4*>(&g_x2sum[(size_t)n * 16]);
        float4 a0 = p[0], a1 = p[1], a2 = p[2], a3 = p[3];
        float vv[15] = { a0.x, a0.y, a0.z, a0.w, a1.x, a1.y, a1.z, a1.w,
                         a2.x, a2.y, a2.z, a2.w, a3.x, a3.y, a3.z };
        float cnt = a3.w;
        float inv = 1.0f / fmaxf(cnt, 1.0f);
        #pragma unroll
        for (int k = 0; k < 15; ++k) {
            float t = vv[k] * inv;
            acc[k] += t;
            acc[15 + k] += fmaxf(t, 0.0f);
        }
    }

    #pragma unroll
    for (int k = 0; k < 30; ++k) {
        float v = acc[k];
        #pragma unroll
        for (int off = 16; off > 0; off >>= 1)
            v += __shfl_down_sync(0xFFFFFFFF, v, off);
        acc[k] = v;
    }
    int wid = tid >> 5, lid = tid & 31;
    if (lid == 0) {
        #pragma unroll
        for (int k = 0; k < 30; ++k) sred[wid][k] = acc[k];
    }
    __syncthreads();

    if (tid == 0) {
        float gsum[15], zsum[15];
        #pragma unroll
        for (int k = 0; k < 15; ++k) { gsum[k] = 0.0f; zsum[k] = 0.0f; }
        for (int w = 0; w < (int)(blockDim.x >> 5); ++w) {
            #pragma unroll
            for (int k = 0; k < 15; ++k) {
                gsum[k] += sred[w][k];
                zsum[k] += sred[w][15 + k];
            }
        }

        float cntf = (float)nnodes;
        float invc = 1.0f / fmaxf(cntf, 1.0f);

        float in16[16];
        in16[0] = u[b];
        #pragma unroll
        for (int k = 0; k < 15; ++k) in16[1 + k] = gsum[k] * invc;

        float hg[D2];
        #pragma unroll
        for (int j = 0; j < D2; ++j) hg[j] = swt[SG_GB1 + j];
        #pragma unroll
        for (int i = 0; i < 16; ++i) {
            float xi = in16[i];
            #pragma unroll
            for (int j = 0; j < D2; ++j) hg[j] += xi * swt[SG_GW1 + i * D2 + j];
        }
        #pragma unroll
        for (int j = 0; j < D2; ++j) hg[j] = fmaxf(hg[j], 0.0f);

        float u2[D3];
        #pragma unroll
        for (int k = 0; k < D3; ++k) u2[k] = swt[SG_GB2 + k];
        #pragma unroll
        for (int j = 0; j < D2; ++j) {
            float hj = hg[j];
            #pragma unroll
            for (int k = 0; k < D3; ++k) u2[k] += hj * swt[SG_GW2 + j * D3 + k];
        }

        float invg = 1.0f / (cntf + 1.0f);
        float g[D3];
        #pragma unroll
        for (int k = 0; k < D3; ++k)
            g[k] = (zsum[k] + fmaxf(u2[k], 0.0f)) * invg;

        float h1[D5];
        #pragma unroll
        for (int m = 0; m < D5; ++m) h1[m] = swt[SG_F1B + m];
        #pragma unroll
        for (int k = 0; k < D3; ++k) {
            float gk = g[k];
            #pragma unroll
            for (int m = 0; m < D5; ++m) h1[m] += gk * swt[SG_F1W + k * D5 + m];
        }

        float rs = rsqrtf(1.0f + 1e-5f);
        #pragma unroll
        for (int m = 0; m < D5; ++m)
            h1[m] = fmaxf(h1[m] * (swt[SG_BNG + m] * rs) + swt[SG_BNB + m], 0.0f);

        float lg[NC];
        #pragma unroll
        for (int q = 0; q < NC; ++q) lg[q] = swt[SG_F2B + q];
        #pragma unroll
        for (int m = 0; m < D5; ++m) {
            float hm = h1[m];
            #pragma unroll
            for (int q = 0; q < NC; ++q) lg[q] += hm * swt[SG_F2W + m * NC + q];
        }

        float mx = lg[0];
        #pragma unroll
        for (int q = 1; q < NC; ++q) mx = fmaxf(mx, lg[q]);
        float ssum = 0.0f;
        #pragma unroll
        for (int q = 0; q < NC; ++q) ssum += expf(lg[q] - mx);
        float lse = mx + logf(ssum);
        #pragma unroll
        for (int q = 0; q < NC; ++q) out[b * NC + q] = lg[q] - lse;
    }
}

// ---------------- launch ----------------
extern "C" void kernel_launch(void* const* d_in, const int* in_sizes, int n_in,
                              void* d_out, int out_size) {
    const float* x     = (const float*)d_in[0];
    const int*   ei    = (const int*)d_in[1];
    const float* ea    = (const float*)d_in[2];
    const float* u     = (const float*)d_in[3];
    const int*   batch = (const int*)d_in[4];
    const float* ew1   = (const float*)d_in[5];
    const float* eb1   = (const float*)d_in[6];
    const float* ew2   = (const float*)d_in[7];
    const float* eb2   = (const float*)d_in[8];
    const float* nw1   = (const float*)d_in[9];
    const float* nb1   = (const float*)d_in[10];
    const float* nw2   = (const float*)d_in[11];
    const float* nb2   = (const float*)d_in[12];
    const float* gw1   = (const float*)d_in[13];
    const float* gb1   = (const float*)d_in[14];
    const float* gw2   = (const float*)d_in[15];
    const float* gb2   = (const float*)d_in[16];
    const float* fc1w  = (const float*)d_in[17];
    const float* fc1b  = (const float*)d_in[18];
    const float* bng   = (const float*)d_in[19];
    const float* bnb   = (const float*)d_in[20];
    const float* fc2w  = (const float*)d_in[21];
    const float* fc2b  = (const float*)d_in[22];
    float* out = (float*)d_out;

    int N = in_sizes[0] / 3;   // nodes
    int E = in_sizes[1] / 2;   // edges
    int B = in_sizes[3];       // graphs

    const int* row = ei;
    const int* col = ei + E;

    zero_kernel<<<512, 256>>>(N);

    int P = (E + 1) / 2;
    edge_kernel<<<(P + 127) / 128, 128>>>(x, row, col, ea,
                                          ew1, eb1, ew2, eb2,
                                          nw1, nb1, nw2, nb2, P, E);

    graph_kernel<<<B, 256>>>(batch, u,
                             gw1, gb1, gw2, gb2,
                             fc1w, fc1b, bng, bnb, fc2w, fc2b, out, N);
}

// round 8
// speedup vs baseline: 1.4662x; 1.4662x over previous
#include <cuda_runtime.h>
#include <math.h>

// Problem dims (fixed by setup_inputs)
#define MAXN 100000
#define MAXB 256
#define D2 50
#define D3 15
#define D2P 52
#define D5 10
#define NC 6

// ---------------- device scratch ----------------
// per-node record: 15 accum floats + count in slot 15 (16 floats = 64B)
__device__ __align__(16) float g_x2sum[MAXN * 16];

// ---------------- packed f32x2 helpers ----------------
__device__ __forceinline__ unsigned long long pack2(float a, float b) {
    unsigned long long r;
    asm("mov.b64 %0, {%1, %2};" : "=l"(r) : "f"(a), "f"(b));
    return r;
}
__device__ __forceinline__ void unpack2(unsigned long long v, float& a, float& b) {
    asm("mov.b64 {%0, %1}, %2;" : "=f"(a), "=f"(b) : "l"(v));
}
__device__ __forceinline__ void ffma2(unsigned long long& acc,
                                      unsigned long long a, unsigned long long b) {
    asm("fma.rn.f32x2 %0, %1, %2, %0;" : "+l"(acc) : "l"(a), "l"(b));
}
__device__ __forceinline__ void red4(float* p, float a, float b, float c, float d) {
    asm volatile("red.global.add.v4.f32 [%0], {%1, %2, %3, %4};"
                 :: "l"(p), "f"(a), "f"(b), "f"(c), "f"(d) : "memory");
}

// ---------------- zero accumulators ----------------
__global__ void zero_kernel(int N) {
    int tid = blockIdx.x * blockDim.x + threadIdx.x;
    int stride = gridDim.x * blockDim.x;
    int total = N * 4;  // float4 units
    float4 z = make_float4(0.f, 0.f, 0.f, 0.f);
    float4* p = reinterpret_cast<float4*>(g_x2sum);
    for (int t = tid; t < total; t += stride) p[t] = z;
}

// ---------------- SMEM weight layout (floats, 16B-aligned offsets) --------
// layer-1 weights: [in][52] padded rows (broadcast multiplicand scheme)
// layer-2 weights: j-pair transposed: [outs][52], float (k*52+j) = w2[j][k]
#define OFF_EW1  0                        // [9][52]
#define OFF_EB1  468                      // [52]
#define OFF_EW2P 520                      // [16][52]
#define OFF_EB2  1352                     // [16]
#define OFF_NW1  1368                     // [18][52]
#define OFF_NB1  2304                     // [52]
#define OFF_NW2P 2356                     // [16][52]
#define OFF_NB2  3188                     // [16]
#define SW_TOTAL 3204

// ---------------- edge kernel: ONE edge/thread, lean register set ---------
__global__ void __launch_bounds__(128)
edge_kernel(
    const float* __restrict__ x,
    const int* __restrict__ row,
    const int* __restrict__ col,
    const float* __restrict__ ea,
    const float* __restrict__ ew1, const float* __restrict__ eb1,
    const float* __restrict__ ew2, const float* __restrict__ eb2,
    const float* __restrict__ nw1, const float* __restrict__ nb1,
    const float* __restrict__ nw2, const float* __restrict__ nb2,
    int E)
{
    __shared__ __align__(16) float sw[SW_TOTAL];

    for (int t = threadIdx.x; t < SW_TOTAL; t += blockDim.x) sw[t] = 0.0f;
    __syncthreads();
    for (int t = threadIdx.x; t < 9 * D2; t += blockDim.x) {
        int i = t / D2, j = t % D2;
        sw[OFF_EW1 + i * D2P + j] = ew1[t];
    }
    for (int t = threadIdx.x; t < D2; t += blockDim.x) sw[OFF_EB1 + t] = eb1[t];
    for (int t = threadIdx.x; t < D2 * D3; t += blockDim.x) {
        int j = t / D3, k = t % D3;
        sw[OFF_EW2P + k * D2P + j] = ew2[t];
    }
    for (int t = threadIdx.x; t < D3; t += blockDim.x) sw[OFF_EB2 + t] = eb2[t];
    for (int t = threadIdx.x; t < 18 * D2; t += blockDim.x) {
        int i = t / D2, j = t % D2;
        sw[OFF_NW1 + i * D2P + j] = nw1[t];
    }
    for (int t = threadIdx.x; t < D2; t += blockDim.x) sw[OFF_NB1 + t] = nb1[t];
    for (int t = threadIdx.x; t < D2 * D3; t += blockDim.x) {
        int j = t / D3, k = t % D3;
        sw[OFF_NW2P + k * D2P + j] = nw2[t];
    }
    for (int t = threadIdx.x; t < D3; t += blockDim.x) sw[OFF_NB2 + t] = nb2[t];
    __syncthreads();

    int e = blockIdx.x * blockDim.x + threadIdx.x;
    if (e >= E) return;

    int r = row[e];
    int c = col[e];

    float in9[9];
    in9[0] = x[3 * r + 0]; in9[1] = x[3 * r + 1]; in9[2] = x[3 * r + 2];
    in9[3] = x[3 * c + 0]; in9[4] = x[3 * c + 1]; in9[5] = x[3 * c + 2];
    in9[6] = ea[3 * e + 0]; in9[7] = ea[3 * e + 1]; in9[8] = ea[3 * e + 2];
    float xc0 = in9[3], xc1 = in9[4], xc2 = in9[5];

    // ==== edge MLP layer 1: h = relu(eb1 + in9 @ ew1)  (26 packed pairs)
    unsigned long long h[26];
    {
        const ulonglong2* bv = reinterpret_cast<const ulonglong2*>(&sw[OFF_EB1]);
        #pragma unroll
        for (int q2 = 0; q2 < 13; ++q2) {
            ulonglong2 b = bv[q2];
            h[2 * q2] = b.x; h[2 * q2 + 1] = b.y;
        }
    }
    #pragma unroll
    for (int i = 0; i < 9; ++i) {
        unsigned long long pa = pack2(in9[i], in9[i]);
        const ulonglong2* wv = reinterpret_cast<const ulonglong2*>(&sw[OFF_EW1 + i * D2P]);
        #pragma unroll
        for (int q2 = 0; q2 < 13; ++q2) {
            ulonglong2 w = wv[q2];
            ffma2(h[2 * q2],     pa, w.x);
            ffma2(h[2 * q2 + 1], pa, w.y);
        }
    }
    #pragma unroll
    for (int q = 0; q < 26; ++q) {
        float a, b;
        unpack2(h[q], a, b);
        h[q] = pack2(fmaxf(a, 0.f), fmaxf(b, 0.f));
    }

    // ==== edge MLP layer 2: e2[k] = eb2[k] + sum_j h[j]*w2[j][k]
    // two independent accumulator chains per k (breaks the serial dep chain)
    float e2f[15];
    #pragma unroll
    for (int k = 0; k < 15; ++k) {
        unsigned long long a0 = 0ULL, a1 = 0ULL;
        const ulonglong2* wp = reinterpret_cast<const ulonglong2*>(&sw[OFF_EW2P + k * D2P]);
        #pragma unroll
        for (int q2 = 0; q2 < 13; ++q2) {
            ulonglong2 w = wp[q2];
            ffma2(a0, h[2 * q2],     w.x);
            ffma2(a1, h[2 * q2 + 1], w.y);
        }
        float l0, h0, l1, h1v;
        unpack2(a0, l0, h0);
        unpack2(a1, l1, h1v);
        e2f[k] = (l0 + h0) + (l1 + h1v) + sw[OFF_EB2 + k];
    }

    // ==== node MLP layer 1: h2 = relu(nb1 + [x[col], e2] @ nw1)
    unsigned long long h2[26];
    {
        const ulonglong2* bv = reinterpret_cast<const ulonglong2*>(&sw[OFF_NB1]);
        #pragma unroll
        for (int q2 = 0; q2 < 13; ++q2) {
            ulonglong2 b = bv[q2];
            h2[2 * q2] = b.x; h2[2 * q2 + 1] = b.y;
        }
    }
    #pragma unroll
    for (int i = 0; i < 18; ++i) {
        float xi;
        if (i == 0)      xi = xc0;
        else if (i == 1) xi = xc1;
        else if (i == 2) xi = xc2;
        else             xi = e2f[i - 3];
        unsigned long long pa = pack2(xi, xi);
        const ulonglong2* wv = reinterpret_cast<const ulonglong2*>(&sw[OFF_NW1 + i * D2P]);
        #pragma unroll
        for (int q2 = 0; q2 < 13; ++q2) {
            ulonglong2 w = wv[q2];
            ffma2(h2[2 * q2],     pa, w.x);
            ffma2(h2[2 * q2 + 1], pa, w.y);
        }
    }
    #pragma unroll
    for (int q = 0; q < 26; ++q) {
        float a, b;
        unpack2(h2[q], a, b);
        h2[q] = pack2(fmaxf(a, 0.f), fmaxf(b, 0.f));
    }

    // ==== node MLP layer 2: o[k] = nb2[k] + sum_j h2[j]*nw2[j][k]
    // emit directly in 4-wide chunks to red4 (no o[] array kept live)
    float* dst = &g_x2sum[(size_t)r * 16];
    #pragma unroll
    for (int kc = 0; kc < 4; ++kc) {
        float v[4];
        #pragma unroll
        for (int t = 0; t < 4; ++t) {
            int k = 4 * kc + t;
            if (k < 15) {
                unsigned long long a0 = 0ULL, a1 = 0ULL;
                const ulonglong2* wp = reinterpret_cast<const ulonglong2*>(&sw[OFF_NW2P + k * D2P]);
                #pragma unroll
                for (int q2 = 0; q2 < 13; ++q2) {
                    ulonglong2 w = wp[q2];
                    ffma2(a0, h2[2 * q2],     w.x);
                    ffma2(a1, h2[2 * q2 + 1], w.y);
                }
                float l0, h0, l1, h1v;
                unpack2(a0, l0, h0);
                unpack2(a1, l1, h1v);
                v[t] = (l0 + h0) + (l1 + h1v) + sw[OFF_NB2 + k];
            } else {
                v[t] = 1.0f;  // count slot
            }
        }
        red4(dst + 4 * kc, v[0], v[1], v[2], v[3]);
    }
}

// ---------------- graph kernel: per-graph reduce + global MLP + head -------
#define SG_GW1 0
#define SG_GB1 (SG_GW1 + 16 * D2)
#define SG_GW2 (SG_GB1 + D2)
#define SG_GB2 (SG_GW2 + D2 * D3)
#define SG_F1W (SG_GB2 + D3)
#define SG_F1B (SG_F1W + D3 * D5)
#define SG_BNG (SG_F1B + D5)
#define SG_BNB (SG_BNG + D5)
#define SG_F2W (SG_BNB + D5)
#define SG_F2B (SG_F2W + D5 * NC)
#define SG_TOTAL (SG_F2B + NC)

__device__ __forceinline__ int lbound(const int* a, int n, int key) {
    int lo = 0, hi = n;
    while (lo < hi) { int m = (lo + hi) >> 1; if (a[m] < key) lo = m + 1; else hi = m; }
    return lo;
}

__global__ void __launch_bounds__(256)
graph_kernel(
    const int* __restrict__ batch,
    const float* __restrict__ u,
    const float* __restrict__ gw1, const float* __restrict__ gb1,
    const float* __restrict__ gw2, const float* __restrict__ gb2,
    const float* __restrict__ fc1w, const float* __restrict__ fc1b,
    const float* __restrict__ bng, const float* __restrict__ bnb,
    const float* __restrict__ fc2w, const float* __restrict__ fc2b,
    float* __restrict__ out, int N)
{
    __shared__ float swt[SG_TOTAL];
    __shared__ float sred[8][30];
    __shared__ int sse[2];

    int tid = threadIdx.x;
    for (int t = tid; t < 16 * D2; t += blockDim.x) swt[SG_GW1 + t] = gw1[t];
    for (int t = tid; t < D2; t += blockDim.x) swt[SG_GB1 + t] = gb1[t];
    for (int t = tid; t < D2 * D3; t += blockDim.x) swt[SG_GW2 + t] = gw2[t];
    for (int t = tid; t < D3; t += blockDim.x) swt[SG_GB2 + t] = gb2[t];
    for (int t = tid; t < D3 * D5; t += blockDim.x) swt[SG_F1W + t] = fc1w[t];
    for (int t = tid; t < D5; t += blockDim.x) {
        swt[SG_F1B + t] = fc1b[t];
        swt[SG_BNG + t] = bng[t];
        swt[SG_BNB + t] = bnb[t];
    }
    for (int t = tid; t < D5 * NC; t += blockDim.x) swt[SG_F2W + t] = fc2w[t];
    for (int t = tid; t < NC; t += blockDim.x) swt[SG_F2B + t] = fc2b[t];

    int b = blockIdx.x;
    if (tid == 0) {
        sse[0] = lbound(batch, N, b);
        sse[1] = lbound(batch, N, b + 1);
    }
    __syncthreads();
    int s = sse[0], epos = sse[1];
    int nnodes = epos - s;

    float acc[30];
    #pragma unroll
    for (int k = 0; k < 30; ++k) acc[k] = 0.0f;

    for (int n = s + tid; n < epos; n += blockDim.x) {
        const float4* p = reinterpret_cast<const float4*>(&g_x2sum[(size_t)n * 16]);
        float4 a0 = p[0], a1 = p[1], a2 = p[2], a3 = p[3];
        float vv[15] = { a0.x, a0.y, a0.z, a0.w, a1.x, a1.y, a1.z, a1.w,
                         a2.x, a2.y, a2.z, a2.w, a3.x, a3.y, a3.z };
        float cnt = a3.w;
        float inv = 1.0f / fmaxf(cnt, 1.0f);
        #pragma unroll
        for (int k = 0; k < 15; ++k) {
            float t = vv[k] * inv;
            acc[k] += t;
            acc[15 + k] += fmaxf(t, 0.0f);
        }
    }

    #pragma unroll
    for (int k = 0; k < 30; ++k) {
        float v = acc[k];
        #pragma unroll
        for (int off = 16; off > 0; off >>= 1)
            v += __shfl_down_sync(0xFFFFFFFF, v, off);
        acc[k] = v;
    }
    int wid = tid >> 5, lid = tid & 31;
    if (lid == 0) {
        #pragma unroll
        for (int k = 0; k < 30; ++k) sred[wid][k] = acc[k];
    }
    __syncthreads();

    if (tid == 0) {
        float gsum[15], zsum[15];
        #pragma unroll
        for (int k = 0; k < 15; ++k) { gsum[k] = 0.0f; zsum[k] = 0.0f; }
        for (int w = 0; w < (int)(blockDim.x >> 5); ++w) {
            #pragma unroll
            for (int k = 0; k < 15; ++k) {
                gsum[k] += sred[w][k];
                zsum[k] += sred[w][15 + k];
            }
        }

        float cntf = (float)nnodes;
        float invc = 1.0f / fmaxf(cntf, 1.0f);

        float in16[16];
        in16[0] = u[b];
        #pragma unroll
        for (int k = 0; k < 15; ++k) in16[1 + k] = gsum[k] * invc;

        float hg[D2];
        #pragma unroll
        for (int j = 0; j < D2; ++j) hg[j] = swt[SG_GB1 + j];
        #pragma unroll
        for (int i = 0; i < 16; ++i) {
            float xi = in16[i];
            #pragma unroll
            for (int j = 0; j < D2; ++j) hg[j] += xi * swt[SG_GW1 + i * D2 + j];
        }
        #pragma unroll
        for (int j = 0; j < D2; ++j) hg[j] = fmaxf(hg[j], 0.0f);

        float u2[D3];
        #pragma unroll
        for (int k = 0; k < D3; ++k) u2[k] = swt[SG_GB2 + k];
        #pragma unroll
        for (int j = 0; j < D2; ++j) {
            float hj = hg[j];
            #pragma unroll
            for (int k = 0; k < D3; ++k) u2[k] += hj * swt[SG_GW2 + j * D3 + k];
        }

        float invg = 1.0f / (cntf + 1.0f);
        float g[D3];
        #pragma unroll
        for (int k = 0; k < D3; ++k)
            g[k] = (zsum[k] + fmaxf(u2[k], 0.0f)) * invg;

        float h1[D5];
        #pragma unroll
        for (int m = 0; m < D5; ++m) h1[m] = swt[SG_F1B + m];
        #pragma unroll
        for (int k = 0; k < D3; ++k) {
            float gk = g[k];
            #pragma unroll
            for (int m = 0; m < D5; ++m) h1[m] += gk * swt[SG_F1W + k * D5 + m];
        }

        float rs = rsqrtf(1.0f + 1e-5f);
        #pragma unroll
        for (int m = 0; m < D5; ++m)
            h1[m] = fmaxf(h1[m] * (swt[SG_BNG + m] * rs) + swt[SG_BNB + m], 0.0f);

        float lg[NC];
        #pragma unroll
        for (int q = 0; q < NC; ++q) lg[q] = swt[SG_F2B + q];
        #pragma unroll
        for (int m = 0; m < D5; ++m) {
            float hm = h1[m];
            #pragma unroll
            for (int q = 0; q < NC; ++q) lg[q] += hm * swt[SG_F2W + m * NC + q];
        }

        float mx = lg[0];
        #pragma unroll
        for (int q = 1; q < NC; ++q) mx = fmaxf(mx, lg[q]);
        float ssum = 0.0f;
        #pragma unroll
        for (int q = 0; q < NC; ++q) ssum += expf(lg[q] - mx);
        float lse = mx + logf(ssum);
        #pragma unroll
        for (int q = 0; q < NC; ++q) out[b * NC + q] = lg[q] - lse;
    }
}

// ---------------- launch ----------------
extern "C" void kernel_launch(void* const* d_in, const int* in_sizes, int n_in,
                              void* d_out, int out_size) {
    const float* x     = (const float*)d_in[0];
    const int*   ei    = (const int*)d_in[1];
    const float* ea    = (const float*)d_in[2];
    const float* u     = (const float*)d_in[3];
    const int*   batch = (const int*)d_in[4];
    const float* ew1   = (const float*)d_in[5];
    const float* eb1   = (const float*)d_in[6];
    const float* ew2   = (const float*)d_in[7];
    const float* eb2   = (const float*)d_in[8];
    const float* nw1   = (const float*)d_in[9];
    const float* nb1   = (const float*)d_in[10];
    const float* nw2   = (const float*)d_in[11];
    const float* nb2   = (const float*)d_in[12];
    const float* gw1   = (const float*)d_in[13];
    const float* gb1   = (const float*)d_in[14];
    const float* gw2   = (const float*)d_in[15];
    const float* gb2   = (const float*)d_in[16];
    const float* fc1w  = (const float*)d_in[17];
    const float* fc1b  = (const float*)d_in[18];
    const float* bng   = (const float*)d_in[19];
    const float* bnb   = (const float*)d_in[20];
    const float* fc2w  = (const float*)d_in[21];
    const float* fc2b  = (const float*)d_in[22];
    float* out = (float*)d_out;

    int N = in_sizes[0] / 3;   // nodes
    int E = in_sizes[1] / 2;   // edges
    int B = in_sizes[3];       // graphs

    const int* row = ei;
    const int* col = ei + E;

    zero_kernel<<<512, 256>>>(N);

    edge_kernel<<<(E + 127) / 128, 128>>>(x, row, col, ea,
                                          ew1, eb1, ew2, eb2,
                                          nw1, nb1, nw2, nb2, E);

    graph_kernel<<<B, 256>>>(batch, u,
                             gw1, gb1, gw2, gb2,
                             fc1w, fc1b, bng, bnb, fc2w, fc2b, out, N);
}

// round 9
// speedup vs baseline: 2.2191x; 1.5135x over previous
#include <cuda_runtime.h>
#include <math.h>

// Problem dims (fixed by setup_inputs)
#define MAXN 100000
#define MAXB 256
#define D2 50
#define D3 15
#define D5 10
#define NC 6

// ---------------- device scratch ----------------
// per-node record: 15 accum floats + count in slot 15 (16 floats = 64B)
__device__ __align__(16) float g_x2sum[MAXN * 16];

// ---------------- packed f32x2 helpers ----------------
__device__ __forceinline__ unsigned long long pack2(float a, float b) {
    unsigned long long r;
    asm("mov.b64 %0, {%1, %2};" : "=l"(r) : "f"(a), "f"(b));
    return r;
}
__device__ __forceinline__ void unpack2(unsigned long long v, float& a, float& b) {
    asm("mov.b64 {%0, %1}, %2;" : "=f"(a), "=f"(b) : "l"(v));
}
__device__ __forceinline__ void ffma2(unsigned long long& acc,
                                      unsigned long long a, unsigned long long b) {
    asm("fma.rn.f32x2 %0, %1, %2, %0;" : "+l"(acc) : "l"(a), "l"(b));
}
__device__ __forceinline__ void red4(float* p, float a, float b, float c, float d) {
    asm volatile("red.global.add.v4.f32 [%0], {%1, %2, %3, %4};"
                 :: "l"(p), "f"(a), "f"(b), "f"(c), "f"(d) : "memory");
}

// ---------------- zero accumulators ----------------
__global__ void zero_kernel(int N) {
    int tid = blockIdx.x * blockDim.x + threadIdx.x;
    int stride = gridDim.x * blockDim.x;
    int total = N * 4;  // float4 units
    float4 z = make_float4(0.f, 0.f, 0.f, 0.f);
    float4* p = reinterpret_cast<float4*>(g_x2sum);
    for (int t = tid; t < total; t += stride) p[t] = z;
}

// ---------------- SMEM weight layout (floats) -----------------------------
// Layer-1 weights chunk-major:  [13 chunks][in][4 j]   (j = ch*4 + jl, pad 52)
// Layer-1 bias:                 [52] linear (j index)
// Layer-2 weights k-pair-major: [52 j][16 k]  (float t = j*16 + k, pad)
// Layer-2 bias:                 [16] linear (k index)
#define OFF_EW1   0                      // 13*9*4  = 468
#define OFF_EB1   468                    // 52
#define OFF_EW2KP 520                    // 52*16   = 832
#define OFF_EB2   1352                   // 16
#define OFF_NW1   1368                   // 13*18*4 = 936
#define OFF_NB1   2304                   // 52
#define OFF_NW2KP 2356                   // 832
#define OFF_NB2   3188                   // 16
#define SW_TOTAL  3204

// ---------------- edge kernel: 4 edges/thread, fused chunk consumption ----
__global__ void __launch_bounds__(128)
edge_kernel(
    const float* __restrict__ x,
    const int* __restrict__ row,
    const int* __restrict__ col,
    const float* __restrict__ ea,
    const float* __restrict__ ew1, const float* __restrict__ eb1,
    const float* __restrict__ ew2, const float* __restrict__ eb2,
    const float* __restrict__ nw1, const float* __restrict__ nb1,
    const float* __restrict__ nw2, const float* __restrict__ nb2,
    int P, int E)
{
    __shared__ __align__(16) float sw[SW_TOTAL];

    // ---- stage weights (remapped layouts) ----
    // EW1: [13][9][4]
    for (int t = threadIdx.x; t < 13 * 9 * 4; t += blockDim.x) {
        int ch = t / 36, rem = t % 36, i = rem / 4, jl = rem % 4;
        int j = ch * 4 + jl;
        sw[OFF_EW1 + t] = (j < D2) ? ew1[i * D2 + j] : 0.0f;
    }
    // EB1: linear 52
    for (int t = threadIdx.x; t < 52; t += blockDim.x)
        sw[OFF_EB1 + t] = (t < D2) ? eb1[t] : 0.0f;
    // EW2KP: [52][16]
    for (int t = threadIdx.x; t < 52 * 16; t += blockDim.x) {
        int j = t / 16, k = t % 16;
        sw[OFF_EW2KP + t] = (j < D2 && k < D3) ? ew2[j * D3 + k] : 0.0f;
    }
    // EB2: linear 16
    for (int t = threadIdx.x; t < 16; t += blockDim.x)
        sw[OFF_EB2 + t] = (t < D3) ? eb2[t] : 0.0f;
    // NW1: [13][18][4]
    for (int t = threadIdx.x; t < 13 * 18 * 4; t += blockDim.x) {
        int ch = t / 72, rem = t % 72, i = rem / 4, jl = rem % 4;
        int j = ch * 4 + jl;
        sw[OFF_NW1 + t] = (j < D2) ? nw1[i * D2 + j] : 0.0f;
    }
    for (int t = threadIdx.x; t < 52; t += blockDim.x)
        sw[OFF_NB1 + t] = (t < D2) ? nb1[t] : 0.0f;
    for (int t = threadIdx.x; t < 52 * 16; t += blockDim.x) {
        int j = t / 16, k = t % 16;
        sw[OFF_NW2KP + t] = (j < D2 && k < D3) ? nw2[j * D3 + k] : 0.0f;
    }
    for (int t = threadIdx.x; t < 16; t += blockDim.x)
        sw[OFF_NB2 + t] = (t < D3) ? nb2[t] : 0.0f;
    __syncthreads();

    int p = blockIdx.x * blockDim.x + threadIdx.x;
    if (p >= P) return;

    int e0 = 4 * p;
    bool full = (e0 + 3 < E);

    // ---- gather indices + inputs for 4 edges ----
    int r[4], c[4];
    float in9[4][9];
    if (full) {
        int4 rr = *reinterpret_cast<const int4*>(row + e0);
        int4 cc = *reinterpret_cast<const int4*>(col + e0);
        r[0] = rr.x; r[1] = rr.y; r[2] = rr.z; r[3] = rr.w;
        c[0] = cc.x; c[1] = cc.y; c[2] = cc.z; c[3] = cc.w;
        const float4* ea4 = reinterpret_cast<const float4*>(ea + 3 * e0);
        float4 a0 = ea4[0], a1 = ea4[1], a2 = ea4[2];
        in9[0][6] = a0.x; in9[0][7] = a0.y; in9[0][8] = a0.z;
        in9[1][6] = a0.w; in9[1][7] = a1.x; in9[1][8] = a1.y;
        in9[2][6] = a1.z; in9[2][7] = a1.w; in9[2][8] = a2.x;
        in9[3][6] = a2.y; in9[3][7] = a2.z; in9[3][8] = a2.w;
    } else {
        #pragma unroll
        for (int e = 0; e < 4; ++e) {
            int idx = min(e0 + e, E - 1);
            r[e] = row[idx]; c[e] = col[idx];
            in9[e][6] = ea[3 * idx + 0];
            in9[e][7] = ea[3 * idx + 1];
            in9[e][8] = ea[3 * idx + 2];
        }
    }
    #pragma unroll
    for (int e = 0; e < 4; ++e) {
        in9[e][0] = x[3 * r[e] + 0];
        in9[e][1] = x[3 * r[e] + 1];
        in9[e][2] = x[3 * r[e] + 2];
        in9[e][3] = x[3 * c[e] + 0];
        in9[e][4] = x[3 * c[e] + 1];
        in9[e][5] = x[3 * c[e] + 2];
    }

    // ================= EDGE MLP (fused layers) =================
    // e2 partials: k-pair packed, bias-initialized
    unsigned long long e2p[4][8];
    {
        const ulonglong2* bv = reinterpret_cast<const ulonglong2*>(&sw[OFF_EB2]);
        #pragma unroll
        for (int q = 0; q < 4; ++q) {
            ulonglong2 b = bv[q];
            #pragma unroll
            for (int e = 0; e < 4; ++e) {
                e2p[e][2 * q + 0] = b.x;
                e2p[e][2 * q + 1] = b.y;
            }
        }
    }
    #pragma unroll
    for (int ch = 0; ch < 13; ++ch) {
        // layer-1 chunk (4 outputs) for 4 edges
        unsigned long long h[4][2];
        {
            ulonglong2 b = *reinterpret_cast<const ulonglong2*>(&sw[OFF_EB1 + 4 * ch]);
            #pragma unroll
            for (int e = 0; e < 4; ++e) { h[e][0] = b.x; h[e][1] = b.y; }
        }
        #pragma unroll
        for (int i = 0; i < 9; ++i) {
            ulonglong2 w = *reinterpret_cast<const ulonglong2*>(
                &sw[OFF_EW1 + (ch * 9 + i) * 4]);
            #pragma unroll
            for (int e = 0; e < 4; ++e) {
                unsigned long long pa = pack2(in9[e][i], in9[e][i]);
                ffma2(h[e][0], pa, w.x);
                ffma2(h[e][1], pa, w.y);
            }
        }
        // relu chunk
        #pragma unroll
        for (int e = 0; e < 4; ++e) {
            float a, b;
            unpack2(h[e][0], a, b); h[e][0] = pack2(fmaxf(a, 0.f), fmaxf(b, 0.f));
            unpack2(h[e][1], a, b); h[e][1] = pack2(fmaxf(a, 0.f), fmaxf(b, 0.f));
        }
        // consume chunk into k-pair partials
        #pragma unroll
        for (int jl = 0; jl < 4; ++jl) {
            int j = ch * 4 + jl;
            const ulonglong2* wp = reinterpret_cast<const ulonglong2*>(
                &sw[OFF_EW2KP + j * 16]);
            ulonglong2 w01 = wp[0], w23 = wp[1], w45 = wp[2], w67 = wp[3];
            #pragma unroll
            for (int e = 0; e < 4; ++e) {
                float a, b;
                unpack2(h[e][jl >> 1], a, b);
                float hj = (jl & 1) ? b : a;
                unsigned long long pj = pack2(hj, hj);
                ffma2(e2p[e][0], pj, w01.x);
                ffma2(e2p[e][1], pj, w01.y);
                ffma2(e2p[e][2], pj, w23.x);
                ffma2(e2p[e][3], pj, w23.y);
                ffma2(e2p[e][4], pj, w45.x);
                ffma2(e2p[e][5], pj, w45.y);
                ffma2(e2p[e][6], pj, w67.x);
                ffma2(e2p[e][7], pj, w67.y);
            }
        }
    }
    // fold e2 partials to scalars (bias already in)
    float e2f[4][15];
    #pragma unroll
    for (int e = 0; e < 4; ++e) {
        #pragma unroll
        for (int kp = 0; kp < 8; ++kp) {
            float lo, hi;
            unpack2(e2p[e][kp], lo, hi);
            if (2 * kp < 15)     e2f[e][2 * kp] = lo;
            if (2 * kp + 1 < 15) e2f[e][2 * kp + 1] = hi;
        }
    }

    // ================= NODE MLP (fused layers) =================
    unsigned long long op[4][8];
    {
        const ulonglong2* bv = reinterpret_cast<const ulonglong2*>(&sw[OFF_NB2]);
        #pragma unroll
        for (int q = 0; q < 4; ++q) {
            ulonglong2 b = bv[q];
            #pragma unroll
            for (int e = 0; e < 4; ++e) {
                op[e][2 * q + 0] = b.x;
                op[e][2 * q + 1] = b.y;
            }
        }
    }
    #pragma unroll
    for (int ch = 0; ch < 13; ++ch) {
        unsigned long long h2[4][2];
        {
            ulonglong2 b = *reinterpret_cast<const ulonglong2*>(&sw[OFF_NB1 + 4 * ch]);
            #pragma unroll
            for (int e = 0; e < 4; ++e) { h2[e][0] = b.x; h2[e][1] = b.y; }
        }
        #pragma unroll
        for (int i = 0; i < 18; ++i) {
            ulonglong2 w = *reinterpret_cast<const ulonglong2*>(
                &sw[OFF_NW1 + (ch * 18 + i) * 4]);
            #pragma unroll
            for (int e = 0; e < 4; ++e) {
                float xi = (i < 3) ? in9[e][3 + i] : e2f[e][i - 3];
                unsigned long long pa = pack2(xi, xi);
                ffma2(h2[e][0], pa, w.x);
                ffma2(h2[e][1], pa, w.y);
            }
        }
        #pragma unroll
        for (int e = 0; e < 4; ++e) {
            float a, b;
            unpack2(h2[e][0], a, b); h2[e][0] = pack2(fmaxf(a, 0.f), fmaxf(b, 0.f));
            unpack2(h2[e][1], a, b); h2[e][1] = pack2(fmaxf(a, 0.f), fmaxf(b, 0.f));
        }
        #pragma unroll
        for (int jl = 0; jl < 4; ++jl) {
            int j = ch * 4 + jl;
            const ulonglong2* wp = reinterpret_cast<const ulonglong2*>(
                &sw[OFF_NW2KP + j * 16]);
            ulonglong2 w01 = wp[0], w23 = wp[1], w45 = wp[2], w67 = wp[3];
            #pragma unroll
            for (int e = 0; e < 4; ++e) {
                float a, b;
                unpack2(h2[e][jl >> 1], a, b);
                float hj = (jl & 1) ? b : a;
                unsigned long long pj = pack2(hj, hj);
                ffma2(op[e][0], pj, w01.x);
                ffma2(op[e][1], pj, w01.y);
                ffma2(op[e][2], pj, w23.x);
                ffma2(op[e][3], pj, w23.y);
                ffma2(op[e][4], pj, w45.x);
                ffma2(op[e][5], pj, w45.y);
                ffma2(op[e][6], pj, w67.x);
                ffma2(op[e][7], pj, w67.y);
            }
        }
    }

    // ---- fold + scatter (slot 15 carries the count 1.0) ----
    #pragma unroll
    for (int e = 0; e < 4; ++e) {
        if (!full && (e0 + e >= E)) break;
        float o[16];
        #pragma unroll
        for (int kp = 0; kp < 8; ++kp)
            unpack2(op[e][kp], o[2 * kp], o[2 * kp + 1]);
        o[15] = 1.0f;
        float* dst = &g_x2sum[(size_t)r[e] * 16];
        red4(dst + 0,  o[0],  o[1],  o[2],  o[3]);
        red4(dst + 4,  o[4],  o[5],  o[6],  o[7]);
        red4(dst + 8,  o[8],  o[9],  o[10], o[11]);
        red4(dst + 12, o[12], o[13], o[14], o[15]);
    }
}

// ---------------- graph kernel: per-graph reduce + global MLP + head -------
#define SG_GW1 0
#define SG_GB1 (SG_GW1 + 16 * D2)
#define SG_GW2 (SG_GB1 + D2)
#define SG_GB2 (SG_GW2 + D2 * D3)
#define SG_F1W (SG_GB2 + D3)
#define SG_F1B (SG_F1W + D3 * D5)
#define SG_BNG (SG_F1B + D5)
#define SG_BNB (SG_BNG + D5)
#define SG_F2W (SG_BNB + D5)
#define SG_F2B (SG_F2W + D5 * NC)
#define SG_TOTAL (SG_F2B + NC)

__device__ __forceinline__ int lbound(const int* a, int n, int key) {
    int lo = 0, hi = n;
    while (lo < hi) { int m = (lo + hi) >> 1; if (a[m] < key) lo = m + 1; else hi = m; }
    return lo;
}

__global__ void __launch_bounds__(256)
graph_kernel(
    const int* __restrict__ batch,
    const float* __restrict__ u,
    const float* __restrict__ gw1, const float* __restrict__ gb1,
    const float* __restrict__ gw2, const float* __restrict__ gb2,
    const float* __restrict__ fc1w, const float* __restrict__ fc1b,
    const float* __restrict__ bng, const float* __restrict__ bnb,
    const float* __restrict__ fc2w, const float* __restrict__ fc2b,
    float* __restrict__ out, int N)
{
    __shared__ float swt[SG_TOTAL];
    __shared__ float sred[8][30];
    __shared__ int sse[2];

    int tid = threadIdx.x;
    for (int t = tid; t < 16 * D2; t += blockDim.x) swt[SG_GW1 + t] = gw1[t];
    for (int t = tid; t < D2; t += blockDim.x) swt[SG_GB1 + t] = gb1[t];
    for (int t = tid; t < D2 * D3; t += blockDim.x) swt[SG_GW2 + t] = gw2[t];
    for (int t = tid; t < D3; t += blockDim.x) swt[SG_GB2 + t] = gb2[t];
    for (int t = tid; t < D3 * D5; t += blockDim.x) swt[SG_F1W + t] = fc1w[t];
    for (int t = tid; t < D5; t += blockDim.x) {
        swt[SG_F1B + t] = fc1b[t];
        swt[SG_BNG + t] = bng[t];
        swt[SG_BNB + t] = bnb[t];
    }
    for (int t = tid; t < D5 * NC; t += blockDim.x) swt[SG_F2W + t] = fc2w[t];
    for (int t = tid; t < NC; t += blockDim.x) swt[SG_F2B + t] = fc2b[t];

    int b = blockIdx.x;
    if (tid == 0) {
        sse[0] = lbound(batch, N, b);
        sse[1] = lbound(batch, N, b + 1);
    }
    __syncthreads();
    int s = sse[0], epos = sse[1];
    int nnodes = epos - s;

    float acc[30];
    #pragma unroll
    for (int k = 0; k < 30; ++k) acc[k] = 0.0f;

    for (int n = s + tid; n < epos; n += blockDim.x) {
        const float4* p = reinterpret_cast<const float4*>(&g_x2sum[(size_t)n * 16]);
        float4 a0 = p[0], a1 = p[1], a2 = p[2], a3 = p[3];
        float vv[15] = { a0.x, a0.y, a0.z, a0.w, a1.x, a1.y, a1.z, a1.w,
                         a2.x, a2.y, a2.z, a2.w, a3.x, a3.y, a3.z };
        float cnt = a3.w;
        float inv = 1.0f / fmaxf(cnt, 1.0f);
        #pragma unroll
        for (int k = 0; k < 15; ++k) {
            float t = vv[k] * inv;
            acc[k] += t;
            acc[15 + k] += fmaxf(t, 0.0f);
        }
    }

    #pragma unroll
    for (int k = 0; k < 30; ++k) {
        float v = acc[k];
        #pragma unroll
        for (int off = 16; off > 0; off >>= 1)
            v += __shfl_down_sync(0xFFFFFFFF, v, off);
        acc[k] = v;
    }
    int wid = tid >> 5, lid = tid & 31;
    if (lid == 0) {
        #pragma unroll
        for (int k = 0; k < 30; ++k) sred[wid][k] = acc[k];
    }
    __syncthreads();

    if (tid == 0) {
        float gsum[15], zsum[15];
        #pragma unroll
        for (int k = 0; k < 15; ++k) { gsum[k] = 0.0f; zsum[k] = 0.0f; }
        for (int w = 0; w < (int)(blockDim.x >> 5); ++w) {
            #pragma unroll
            for (int k = 0; k < 15; ++k) {
                gsum[k] += sred[w][k];
                zsum[k] += sred[w][15 + k];
            }
        }

        float cntf = (float)nnodes;
        float invc = 1.0f / fmaxf(cntf, 1.0f);

        float in16[16];
        in16[0] = u[b];
        #pragma unroll
        for (int k = 0; k < 15; ++k) in16[1 + k] = gsum[k] * invc;

        float hg[D2];
        #pragma unroll
        for (int j = 0; j < D2; ++j) hg[j] = swt[SG_GB1 + j];
        #pragma unroll
        for (int i = 0; i < 16; ++i) {
            float xi = in16[i];
            #pragma unroll
            for (int j = 0; j < D2; ++j) hg[j] += xi * swt[SG_GW1 + i * D2 + j];
        }
        #pragma unroll
        for (int j = 0; j < D2; ++j) hg[j] = fmaxf(hg[j], 0.0f);

        float u2[D3];
        #pragma unroll
        for (int k = 0; k < D3; ++k) u2[k] = swt[SG_GB2 + k];
        #pragma unroll
        for (int j = 0; j < D2; ++j) {
            float hj = hg[j];
            #pragma unroll
            for (int k = 0; k < D3; ++k) u2[k] += hj * swt[SG_GW2 + j * D3 + k];
        }

        float invg = 1.0f / (cntf + 1.0f);
        float g[D3];
        #pragma unroll
        for (int k = 0; k < D3; ++k)
            g[k] = (zsum[k] + fmaxf(u2[k], 0.0f)) * invg;

        float h1[D5];
        #pragma unroll
        for (int m = 0; m < D5; ++m) h1[m] = swt[SG_F1B + m];
        #pragma unroll
        for (int k = 0; k < D3; ++k) {
            float gk = g[k];
            #pragma unroll
            for (int m = 0; m < D5; ++m) h1[m] += gk * swt[SG_F1W + k * D5 + m];
        }

        float rs = rsqrtf(1.0f + 1e-5f);
        #pragma unroll
        for (int m = 0; m < D5; ++m)
            h1[m] = fmaxf(h1[m] * (swt[SG_BNG + m] * rs) + swt[SG_BNB + m], 0.0f);

        float lg[NC];
        #pragma unroll
        for (int q = 0; q < NC; ++q) lg[q] = swt[SG_F2B + q];
        #pragma unroll
        for (int m = 0; m < D5; ++m) {
            float hm = h1[m];
            #pragma unroll
            for (int q = 0; q < NC; ++q) lg[q] += hm * swt[SG_F2W + m * NC + q];
        }

        float mx = lg[0];
        #pragma unroll
        for (int q = 1; q < NC; ++q) mx = fmaxf(mx, lg[q]);
        float ssum = 0.0f;
        #pragma unroll
        for (int q = 0; q < NC; ++q) ssum += expf(lg[q] - mx);
        float lse = mx + logf(ssum);
        #pragma unroll
        for (int q = 0; q < NC; ++q) out[b * NC + q] = lg[q] - lse;
    }
}

// ---------------- launch ----------------
extern "C" void kernel_launch(void* const* d_in, const int* in_sizes, int n_in,
                              void* d_out, int out_size) {
    const float* x     = (const float*)d_in[0];
    const int*   ei    = (const int*)d_in[1];
    const float* ea    = (const float*)d_in[2];
    const float* u     = (const float*)d_in[3];
    const int*   batch = (const int*)d_in[4];
    const float* ew1   = (const float*)d_in[5];
    const float* eb1   = (const float*)d_in[6];
    const float* ew2   = (const float*)d_in[7];
    const float* eb2   = (const float*)d_in[8];
    const float* nw1   = (const float*)d_in[9];
    const float* nb1   = (const float*)d_in[10];
    const float* nw2   = (const float*)d_in[11];
    const float* nb2   = (const float*)d_in[12];
    const float* gw1   = (const float*)d_in[13];
    const float* gb1   = (const float*)d_in[14];
    const float* gw2   = (const float*)d_in[15];
    const float* gb2   = (const float*)d_in[16];
    const float* fc1w  = (const float*)d_in[17];
    const float* fc1b  = (const float*)d_in[18];
    const float* bng   = (const float*)d_in[19];
    const float* bnb   = (const float*)d_in[20];
    const float* fc2w  = (const float*)d_in[21];
    const float* fc2b  = (const float*)d_in[22];
    float* out = (float*)d_out;

    int N = in_sizes[0] / 3;   // nodes
    int E = in_sizes[1] / 2;   // edges
    int B = in_sizes[3];       // graphs

    const int* row = ei;
    const int* col = ei + E;

    zero_kernel<<<512, 256>>>(N);

    int P = (E + 3) / 4;       // 4 edges per thread
    edge_kernel<<<(P + 127) / 128, 128>>>(x, row, col, ea,
                                          ew1, eb1, ew2, eb2,
                                          nw1, nb1, nw2, nb2, P, E);

    graph_kernel<<<B, 256>>>(batch, u,
                             gw1, gb1, gw2, gb2,
                             fc1w, fc1b, bng, bnb, fc2w, fc2b, out, N);
}